// round 13
// baseline (speedup 1.0000x reference)
#include <cuda_runtime.h>
#include <cuda_fp16.h>
#include <math.h>
#include <cstdint>

#define BB 8
#define CC 128
#define HS 62
#define WS 62
#define HH 64
#define WW 64
#define GG 4
#define PP 9

// ---------------------------------------------------------------------------
// Scratch
// ---------------------------------------------------------------------------
__device__ float g_y     [BB*HH*WW*CC];
__device__ float g_xproj [BB*HH*WW*CC];
__device__ float g_d     [BB*HH*WW*CC];
__device__ float g_om    [BB*HH*WW*CC];
__device__ float g_samp  [BB*HH*WW*CC];
__device__ float g_Bimg  [4*CC*CC];      // B fragment blobs (m=1..3 used), tf32
__device__ float g_bcomb [CC];

__device__ __forceinline__ uint32_t f2tf32(float f) {
    uint32_t u;
    asm("cvt.rna.tf32.f32 %0, %1;" : "=r"(u) : "f"(f));
    return u;
}
__device__ __forceinline__ float f2tf32f(float f) {
    return __uint_as_float(f2tf32(f));
}
__device__ __forceinline__ uint32_t s2u(const void* p) {
    return (uint32_t)__cvta_generic_to_shared(p);
}
__device__ __forceinline__ void cp_async16(uint32_t dst, const void* src) {
    asm volatile("cp.async.cg.shared.global [%0], [%1], 16;" :: "r"(dst), "l"(src));
}
__device__ __forceinline__ void cp_async16_z(uint32_t dst, const void* src, int vsize) {
    asm volatile("cp.async.cg.shared.global [%0], [%1], 16, %2;"
                 :: "r"(dst), "l"(src), "r"(vsize));
}
#define CP_COMMIT() asm volatile("cp.async.commit_group;" ::: "memory")
#define CP_WAIT(n)  asm volatile("cp.async.wait_group %0;" :: "n"(n) : "memory")

// ---------------------------------------------------------------------------
// Shared GEMM geometry. B blob: 16384 floats, no padding.
// ---------------------------------------------------------------------------
#define ASTR 36
#define CSTR 132
#define OFF_B 0
#define OFF_A0 16384
#define OFF_A1 (16384 + 128*ASTR)
#define OFF_BIAS (16384 + 2*128*ASTR)
#define SMEM_FLOATS (16384 + 2*128*ASTR + 128)
#define SMEM_BYTES (SMEM_FLOATS * 4)

#define DECL_ACC                                                              \
    float acc[2][8][4];                                                       \
    _Pragma("unroll") for (int i = 0; i < 2; i++)                             \
    _Pragma("unroll") for (int j = 0; j < 8; j++)                             \
    _Pragma("unroll") for (int q = 0; q < 4; q++) acc[i][j][q] = 0.f;

#define COMPUTE_CHUNK(kc)                                                     \
do {                                                                          \
    const float* As = smem + (((kc) & 1) ? OFF_A1 : OFF_A0);                  \
    _Pragma("unroll")                                                         \
    for (int ks = 0; ks < 4; ks++) {                                          \
        int k0 = ks * 8;                                                      \
        uint32_t a[2][4];                                                     \
        _Pragma("unroll")                                                     \
        for (int rg = 0; rg < 2; rg++) {                                      \
            const float* ab = As + (wr * 32 + rg * 16 + lg) * ASTR + k0 + lk; \
            a[rg][0] = __float_as_uint(ab[0]);                                \
            a[rg][1] = __float_as_uint(ab[8 * ASTR]);                         \
            a[rg][2] = __float_as_uint(ab[4]);                                \
            a[rg][3] = __float_as_uint(ab[8 * ASTR + 4]);                     \
        }                                                                     \
        const float4* bb = (const float4*)(smem + OFF_B)                      \
                         + (((wc * 16 + (kc) * 4 + ks) * 4) * 32 + lane);     \
        float4 q0 = bb[0], q1 = bb[32], q2 = bb[64], q3 = bb[96];             \
        uint32_t bfr[8][2];                                                   \
        bfr[0][0] = __float_as_uint(q0.x); bfr[0][1] = __float_as_uint(q0.y); \
        bfr[1][0] = __float_as_uint(q0.z); bfr[1][1] = __float_as_uint(q0.w); \
        bfr[2][0] = __float_as_uint(q1.x); bfr[2][1] = __float_as_uint(q1.y); \
        bfr[3][0] = __float_as_uint(q1.z); bfr[3][1] = __float_as_uint(q1.w); \
        bfr[4][0] = __float_as_uint(q2.x); bfr[4][1] = __float_as_uint(q2.y); \
        bfr[5][0] = __float_as_uint(q2.z); bfr[5][1] = __float_as_uint(q2.w); \
        bfr[6][0] = __float_as_uint(q3.x); bfr[6][1] = __float_as_uint(q3.y); \
        bfr[7][0] = __float_as_uint(q3.z); bfr[7][1] = __float_as_uint(q3.w); \
        _Pragma("unroll")                                                     \
        for (int rg = 0; rg < 2; rg++)                                        \
        _Pragma("unroll")                                                     \
        for (int nf = 0; nf < 8; nf++) {                                      \
            asm volatile(                                                     \
                "mma.sync.aligned.m16n8k8.row.col.f32.tf32.tf32.f32 "         \
                "{%0,%1,%2,%3}, {%4,%5,%6,%7}, {%8,%9}, {%0,%1,%2,%3};"       \
                : "+f"(acc[rg][nf][0]), "+f"(acc[rg][nf][1]),                 \
                  "+f"(acc[rg][nf][2]), "+f"(acc[rg][nf][3])                  \
                : "r"(a[rg][0]), "r"(a[rg][1]), "r"(a[rg][2]), "r"(a[rg][3]), \
                  "r"(bfr[nf][0]), "r"(bfr[nf][1]));                          \
        }                                                                     \
    }                                                                         \
} while (0)

#define ISSUE_A(ck, buf)                                                      \
do {                                                                          \
    float* As_ = smem + ((buf) ? OFF_A1 : OFF_A0);                            \
    int k0_ = (ck) * 32;                                                      \
    _Pragma("unroll")                                                         \
    for (int j = 0; j < 4; j++) {                                             \
        int f4 = tid + j * 256;                                               \
        int r = f4 >> 3, kq = (f4 & 7) * 4;                                   \
        cp_async16(s2u(As_ + r * ASTR + kq),                                  \
                   A + (size_t)(row0 + r) * 128 + k0_ + kq);                  \
    }                                                                         \
} while (0)

// Core async GEMM body (A tf32-pre-rounded, M mult of 128)
__device__ __forceinline__ void gemm_body(
        float* smem, const float* __restrict__ A, const float* __restrict__ Bimg,
        const float* __restrict__ bias, float* __restrict__ Cmat,
        int row0, int mode) {
    float* sbias = smem + OFF_BIAS;
    int tid = threadIdx.x;
    int lane = tid & 31;
    int wid = tid >> 5;

    if (tid < 128) sbias[tid] = bias[tid];

#pragma unroll
    for (int j = 0; j < 16; j++) {
        int f4 = tid + j * 256;
        cp_async16(s2u(smem + OFF_B + f4 * 4), Bimg + f4 * 4);
    }
    ISSUE_A(0, 0);
    CP_COMMIT();
    ISSUE_A(1, 1);
    CP_COMMIT();
    CP_WAIT(1);
    __syncthreads();

    int wr = wid >> 1;
    int wc = wid & 1;
    int lg = lane >> 2;
    int lk = lane & 3;
    DECL_ACC;

#pragma unroll
    for (int kc = 0; kc < 4; kc++) {
        COMPUTE_CHUNK(kc);
        if (kc < 3) {
            __syncthreads();
            if (kc < 2) {
                ISSUE_A(kc + 2, kc & 1);
                CP_COMMIT();
                CP_WAIT(1);
            } else {
                CP_WAIT(0);
            }
            __syncthreads();
        }
    }

    if (mode == 2) {
        __syncthreads();
        float* Cs = smem;
#pragma unroll
        for (int rg = 0; rg < 2; rg++)
#pragma unroll
            for (int half = 0; half < 2; half++) {
                int r = wr * 32 + rg * 16 + lg + half * 8;
#pragma unroll
                for (int nf = 0; nf < 8; nf++) {
                    int col = wc * 64 + nf * 8 + 2 * lk;
                    Cs[col * CSTR + r]       = acc[rg][nf][half * 2 + 0] + sbias[col];
                    Cs[(col + 1) * CSTR + r] = acc[rg][nf][half * 2 + 1] + sbias[col + 1];
                }
            }
        __syncthreads();
        int bimg2 = row0 >> 12;
        int pix0 = row0 & 4095;
#pragma unroll
        for (int j = 0; j < 16; j++) {
            int f4 = tid + j * 256;
            int ch = f4 >> 5, p4 = (f4 & 31) * 4;
            float4 v = *(const float4*)(Cs + ch * CSTR + p4);
            *(float4*)(Cmat + (size_t)(bimg2 * 128 + ch) * 4096 + pix0 + p4) = v;
        }
        return;
    }

#pragma unroll
    for (int rg = 0; rg < 2; rg++)
#pragma unroll
        for (int half = 0; half < 2; half++) {
            int row = row0 + wr * 32 + rg * 16 + lg + half * 8;
            float* cr = Cmat + (size_t)row * 128;
#pragma unroll
            for (int nf = 0; nf < 8; nf++) {
                int col = wc * 64 + nf * 8 + 2 * lk;
                float2 o;
                o.x = acc[rg][nf][half * 2 + 0] + sbias[col];
                o.y = acc[rg][nf][half * 2 + 1] + sbias[col + 1];
                *(float2*)(cr + col) = o;
            }
        }
}

__global__ __launch_bounds__(256, 2) void mma_gemm_async(
        const float* __restrict__ A, const float* __restrict__ Bimg,
        const float* __restrict__ bias, float* __restrict__ Cmat,
        int M, int mode) {
    extern __shared__ float smem[];
    gemm_body(smem, A, Bimg, bias, Cmat, blockIdx.x * 128, mode);
    (void)M;
}

// ---------------------------------------------------------------------------
// Fused stage 1: blocks 0..240 -> GEMM1 (NCHW x -> y interior);
// blocks 241..432 -> B blobs m=1..3; blocks 433..1440 -> border ring of y.
// ---------------------------------------------------------------------------
__global__ __launch_bounds__(256, 2) void fused_prep_nchw(
        const float* __restrict__ A, const float* __restrict__ conv_w,
        const float* __restrict__ in_proj_w,
        const float* __restrict__ off_w, const float* __restrict__ off_b,
        const float* __restrict__ mask_w, const float* __restrict__ mask_b,
        const float* __restrict__ out_proj_w,
        const float* __restrict__ conv_b, int M) {
    extern __shared__ float smem[];
    int tid = threadIdx.x;
    int blk = blockIdx.x;

    if (blk >= 241) {
        if (blk < 433) {
            int m = 1 + ((blk - 241) >> 6);
            int inner = (blk - 241) & 63;
            int idx = m * 16384 + inner * 256 + tid;
            int f = idx & 16383;
            int f4 = f >> 2, comp = f & 3;
            int lane_ = f4 & 31;
            int t = f4 >> 5;
            int q = t & 3; t >>= 2;
            int ks = t & 15;
            int wcx = t >> 4;
            int nf = 2 * q + (comp >> 1);
            int n = wcx * 64 + nf * 8 + (lane_ >> 2);
            int k = ks * 8 + (lane_ & 3) + ((comp & 1) << 2);
            float v = 0.f;
            if (m == 1) v = in_proj_w[k * CC + n];
            else if (m == 2) {
                if (n < 72)       v = off_w[k * 72 + n];
                else if (n < 108) v = mask_w[k * 36 + (n - 72)];
            } else v = out_proj_w[k * CC + n];
            ((uint32_t*)g_Bimg)[idx] = f2tf32(v);
            if (blk == 241 && tid < CC)
                g_bcomb[tid] = (tid < 72) ? off_b[tid]
                             : (tid < 108 ? mask_b[tid - 72] : 0.f);
        } else {
            int idx = (blk - 433) * 256 + tid;
            int b = idx / (252 * 128);
            int r = idx - b * (252 * 128);
            int pi = r >> 7, c = r & 127;
            int h, w;
            if (pi < 64)       { h = 0;        w = pi; }
            else if (pi < 128) { h = 63;       w = pi - 64; }
            else if (pi < 190) { h = pi - 127; w = 0; }
            else               { h = pi - 189; w = 63; }
            g_y[((size_t)(b * 4096 + h * 64 + w)) * 128 + c] = f2tf32f(conv_b[c]);
        }
        return;
    }

    // ---- NCHW GEMM tile ----
    float* sbias = smem + OFF_BIAS;
    int lane = tid & 31;
    int wid = tid >> 5;
    int row0 = blk * 128;

    if (tid < 128) sbias[tid] = conv_b[tid];

#pragma unroll
    for (int j = 0; j < 16; j++) {
        int f4i = tid + j * 256;
        int lane_ = f4i & 31;
        int t = f4i >> 5;
        int q = t & 3; t >>= 2;
        int ks = t & 15;
        int wcx = t >> 4;
        int lg_ = lane_ >> 2, lk_ = lane_ & 3;
        int n0 = wcx * 64 + (2 * q) * 8 + lg_;
        int n1 = n0 + 8;
        int k0 = ks * 8 + lk_;
        uint4 u;
        u.x = f2tf32(conv_w[n0 * 128 + k0]);
        u.y = f2tf32(conv_w[n0 * 128 + k0 + 4]);
        u.z = f2tf32(conv_w[n1 * 128 + k0]);
        u.w = f2tf32(conv_w[n1 * 128 + k0 + 4]);
        *(uint4*)(smem + OFF_B + f4i * 4) = u;
    }

    float rstage[16];
#define PREFETCH1(kc)                                                         \
do {                                                                          \
    int k0 = (kc) * 32;                                                       \
    _Pragma("unroll")                                                         \
    for (int j = 0; j < 16; j++) {                                            \
        int idx = tid + j * 256;                                              \
        int r = idx & 127, cl = idx >> 7;                                     \
        int grow = row0 + r; if (grow >= M) grow = M - 1;                     \
        int b = grow / 3844;                                                  \
        int s = grow - b * 3844;                                              \
        rstage[j] = A[(size_t)(b * 128 + k0 + cl) * 3844 + s];                \
    }                                                                         \
} while (0)
#define STORE1(buf)                                                           \
do {                                                                          \
    float* As_ = smem + ((buf) ? OFF_A1 : OFF_A0);                            \
    _Pragma("unroll")                                                         \
    for (int j = 0; j < 16; j++) {                                            \
        int idx = tid + j * 256;                                              \
        int r = idx & 127, cl = idx >> 7;                                     \
        ((uint32_t*)(As_ + r * ASTR + cl))[0] = f2tf32(rstage[j]);            \
    }                                                                         \
} while (0)

    PREFETCH1(0);
    STORE1(0);
    __syncthreads();

    int wr = wid >> 1;
    int wc = wid & 1;
    int lg = lane >> 2;
    int lk = lane & 3;
    DECL_ACC;

#pragma unroll
    for (int kc = 0; kc < 4; kc++) {
        if (kc < 3) PREFETCH1(kc + 1);
        COMPUTE_CHUNK(kc);
        if (kc < 3) {
            STORE1((kc + 1) & 1);
            __syncthreads();
        }
    }

#pragma unroll
    for (int rg = 0; rg < 2; rg++)
#pragma unroll
        for (int half = 0; half < 2; half++) {
            int row = row0 + wr * 32 + rg * 16 + lg + half * 8;
            if (row < M) {
                int b2 = row / 3844;
                int r = row - b2 * 3844;
                int hh = r / 62;
                int ww2 = r - hh * 62;
                float* cr = g_y + ((size_t)(b2 * 4096 + (hh + 1) * 64 + ww2 + 1)) * 128;
#pragma unroll
                for (int nf = 0; nf < 8; nf++) {
                    int col = wc * 64 + nf * 8 + 2 * lk;
                    float2 o;
                    o.x = f2tf32f(acc[rg][nf][half * 2 + 0] + sbias[col]);
                    o.y = f2tf32f(acc[rg][nf][half * 2 + 1] + sbias[col + 1]);
                    *(float2*)(cr + col) = o;
                }
            }
        }
#undef PREFETCH1
#undef STORE1
}

// ---------------------------------------------------------------------------
// dw body (tiled): blk in [0,512), 8x8 pixel tile, patch 10x10x128
// ---------------------------------------------------------------------------
__device__ __forceinline__ void dw_body(
        float* patch, int blk,
        const float* __restrict__ dw_w, const float* __restrict__ dw_b,
        const float* __restrict__ ln_g, const float* __restrict__ ln_b) {
    int b = blk >> 6;
    int tile = blk & 63;
    int h0 = (tile >> 3) * 8, w0 = (tile & 7) * 8;
    int tid = threadIdx.x;
    int lane = tid & 31;
    int warp = tid >> 5;

#pragma unroll
    for (int j = 0; j < 13; j++) {
        int idx = tid + j * 256;
        if (idx < 3200) {
            int pos = idx >> 5, q = idx & 31;
            int py = pos / 10, px = pos - py * 10;
            int hh = h0 - 1 + py, ww = w0 - 1 + px;
            bool valid = ((unsigned)hh < 64u) && ((unsigned)ww < 64u);
            int hc = valid ? hh : 0, wc2 = valid ? ww : 0;
            cp_async16_z(s2u(patch + pos * 128 + q * 4),
                         g_y + ((size_t)(b * 4096 + hc * 64 + wc2)) * 128 + q * 4,
                         valid ? 16 : 0);
        }
    }
    CP_COMMIT();

    int c0 = lane * 4;
    float4 wv[9];
#pragma unroll
    for (int t = 0; t < 9; t++) {
        wv[t].x = dw_w[(c0 + 0) * 9 + t];
        wv[t].y = dw_w[(c0 + 1) * 9 + t];
        wv[t].z = dw_w[(c0 + 2) * 9 + t];
        wv[t].w = dw_w[(c0 + 3) * 9 + t];
    }
    float4 bv = *(const float4*)(dw_b + c0);
    float4 gv = *(const float4*)(ln_g + c0);
    float4 lbv = *(const float4*)(ln_b + c0);

    CP_WAIT(0);
    __syncthreads();

#pragma unroll
    for (int i = 0; i < 8; i++) {
        int pix = warp * 8 + i;
        int py = pix >> 3, px = pix & 7;
        float4 acc = bv;
#pragma unroll
        for (int kh = 0; kh < 3; kh++)
#pragma unroll
            for (int kw = 0; kw < 3; kw++) {
                float4 v = *(const float4*)(patch + ((py + kh) * 10 + (px + kw)) * 128 + c0);
                acc.x += v.x * wv[kh * 3 + kw].x;
                acc.y += v.y * wv[kh * 3 + kw].y;
                acc.z += v.z * wv[kh * 3 + kw].z;
                acc.w += v.w * wv[kh * 3 + kw].w;
            }
        float s  = acc.x + acc.y + acc.z + acc.w;
        float s2 = acc.x * acc.x + acc.y * acc.y + acc.z * acc.z + acc.w * acc.w;
#pragma unroll
        for (int o = 16; o; o >>= 1) {
            s  += __shfl_xor_sync(0xffffffffu, s,  o);
            s2 += __shfl_xor_sync(0xffffffffu, s2, o);
        }
        float mu  = s * (1.f / 128.f);
        float var = s2 * (1.f / 128.f) - mu * mu;
        float rstd = rsqrtf(var + 1e-5f);
        float4 o4;
        float v0 = (acc.x - mu) * rstd * gv.x + lbv.x;
        float v1 = (acc.y - mu) * rstd * gv.y + lbv.y;
        float v2 = (acc.z - mu) * rstd * gv.z + lbv.z;
        float v3 = (acc.w - mu) * rstd * gv.w + lbv.w;
        o4.x = f2tf32f(0.5f * v0 * (1.f + erff(v0 * 0.70710678118654752440f)));
        o4.y = f2tf32f(0.5f * v1 * (1.f + erff(v1 * 0.70710678118654752440f)));
        o4.z = f2tf32f(0.5f * v2 * (1.f + erff(v2 * 0.70710678118654752440f)));
        o4.w = f2tf32f(0.5f * v3 * (1.f + erff(v3 * 0.70710678118654752440f)));
        size_t gp = (size_t)(b * 4096 + (h0 + py) * 64 + (w0 + px)) * 128 + c0;
        *(float4*)(g_d + gp) = o4;
    }
}

// ---------------------------------------------------------------------------
// Fused stage 2: blocks 0..255 -> in_proj GEMM (y->xproj);
//                blocks 256..767 -> dw+LN+GELU (y->d).
// ---------------------------------------------------------------------------
__global__ __launch_bounds__(256, 2) void fused_inproj_dw(
        const float* __restrict__ Bimg, const float* __restrict__ in_proj_b,
        const float* __restrict__ dw_w, const float* __restrict__ dw_b,
        const float* __restrict__ ln_g, const float* __restrict__ ln_b) {
    extern __shared__ float smem[];
    if (blockIdx.x < 256) {
        gemm_body(smem, g_y, Bimg, in_proj_b, g_xproj, blockIdx.x * 128, 0);
    } else {
        dw_body(smem, blockIdx.x - 256, dw_w, dw_b, ln_g, ln_b);
    }
}

// ---------------------------------------------------------------------------
// Tiled DCNv3 core: block = (tile, group). 2048 blocks.
// fp16 patch [py14][px14][ch32] (64B/pos, x-pair = 128B contiguous).
// plan: 32B/item {wx_top, wx_bot, wy_top, wy_bot, meta}.
// Gather: lane = (xsel = lane>>4, chpair = lane&15); 2 LDS per point.
// smem: patch_h 12544B | plan 18432B | mask 2304B = 33,280B -> 5+ CTA/SM
// ---------------------------------------------------------------------------
#define DCN_PLAN_OFF 3136              // floats (12544B patch)
#define DCN_MASK_OFF (3136 + 4608)     // plan = 576*8 floats
#define DCN_SMEM_FLOATS (3136 + 4608 + 576)
#define DCN_SMEM_BYTES (DCN_SMEM_FLOATS * 4)

__global__ __launch_bounds__(256, 5) void dcn_core_tiled() {
    extern __shared__ float smem[];
    __half* patchh = (__half*)smem;                 // [196][32]
    float* plan  = smem + DCN_PLAN_OFF;             // [576][8]
    float* smask = smem + DCN_MASK_OFF;             // [576]
    int blk = blockIdx.x;
    int g = blk & 3;
    int tileid = blk >> 2;
    int b = tileid >> 6;
    int tile = tileid & 63;
    int h0 = (tile >> 3) * 8, w0 = (tile & 7) * 8;
    int tid = threadIdx.x;
    int lane = tid & 31;
    int warp = tid >> 5;
    const float* xp = g_xproj + (size_t)b * 4096 * 128;
    const float* omb = g_om + (size_t)b * 4096 * 128;

    // patch fill: 196 pos x 16 ch-pairs, f32 global -> half2 smem
#pragma unroll
    for (int j = 0; j < 13; j++) {
        int idx = tid + j * 256;
        if (idx < 3136) {
            int pos = idx >> 4, c2 = idx & 15;
            int py = pos / 14, px = pos - py * 14;
            int iy = h0 - 3 + py, ix2 = w0 - 3 + px;
            __half2 hv = __floats2half2_rn(0.f, 0.f);
            if (((unsigned)iy < 64u) && ((unsigned)ix2 < 64u)) {
                float2 v = *(const float2*)(xp + ((size_t)(iy * 64 + ix2)) * 128
                                            + g * 32 + c2 * 2);
                hv = __floats2half2_rn(v.x, v.y);
            }
            *(__half2*)((char*)patchh + pos * 64 + c2 * 4) = hv;
        }
    }

    // softmax for this group's mask: thread = pixel (direct global reads)
    if (tid < 64) {
        int lpix = (h0 + (tid >> 3)) * 64 + w0 + (tid & 7);
        const float* mp = omb + (size_t)lpix * 128 + 72 + g * 9;
        float v[9];
        float mx = -1e30f;
#pragma unroll
        for (int i = 0; i < 9; i++) { v[i] = mp[i]; mx = fmaxf(mx, v[i]); }
        float sum = 0.f;
#pragma unroll
        for (int i = 0; i < 9; i++) { v[i] = expf(v[i] - mx); sum += v[i]; }
        float inv = 1.f / sum;
#pragma unroll
        for (int i = 0; i < 9; i++) smask[tid * 9 + i] = v[i] * inv;
    }
    __syncthreads();

    // plan: 576 items = (pix, p)
#pragma unroll
    for (int j = 0; j < 3; j++) {
        int item = tid + j * 256;
        if (item < 576) {
            int pix = item / 9, p = item - pix * 9;
            int w = w0 + (pix & 7), h = h0 + (pix >> 3);
            int lpix = h * 64 + w;
            float2 off = *(const float2*)(omb + (size_t)lpix * 128 + (g * 9 + p) * 2);
            float mv = smask[pix * 9 + p];
            float ix = (float)(w + (p / 3)) + off.x;
            float iy = (float)(h + (p % 3)) + off.y;
            float x0f = floorf(ix), y0f = floorf(iy);
            int x0 = (int)x0f, y0 = (int)y0f;
            float fx = ix - x0f, fy = iy - y0f;
            float wx0 = 1.f - fx, wy0 = 1.f - fy;
            float* pl = plan + item * 8;
            pl[0] = mv * wx0 * wy0;   // x0 top
            pl[1] = mv * wx0 * fy;    // x0 bottom
            pl[2] = mv * fx * wy0;    // x1 top
            pl[3] = mv * fx * fy;     // x1 bottom
            int px0 = x0 - w0 + 2, py0 = y0 - h0 + 2;
            int meta;
            if ((unsigned)px0 <= 12u && (unsigned)py0 <= 12u) {
                meta = (py0 * 14 + px0) * 64;   // byte offset into patchh
            } else {
                int x0c = min(max(x0, -4), 68) + 4;
                int y0c = min(max(y0, -4), 68) + 4;
                meta = (int)(0x80000000u | (unsigned)(y0c << 8) | (unsigned)x0c);
            }
            ((int*)pl)[4] = meta;
        }
    }
    __syncthreads();

    // gather: warp -> 8 pixels; lane = (xsel, chpair)
    int xsel = lane >> 4;        // 0: x0 corners, 1: x1 corners
    int cp = lane & 15;          // channel pair -> ch (2cp, 2cp+1)
#pragma unroll
    for (int i = 0; i < 8; i++) {
        int pix = warp * 8 + i;
        float ax = 0.f, ay = 0.f;
#pragma unroll
        for (int p = 0; p < 9; p++) {
            const float* pl = plan + (pix * 9 + p) * 8;
            float2 wsel = *(const float2*)(pl + xsel * 2);  // (top, bottom)
            int meta = ((const int*)pl)[4];
            if (meta >= 0) {
                const char* base = (const char*)patchh + meta + lane * 4;
                uint32_t tw = *(const uint32_t*)base;          // top row x-pair
                uint32_t bw = *(const uint32_t*)(base + 896);  // bottom row
                float2 vt = __half22float2(*(__half2*)&tw);
                float2 vb = __half22float2(*(__half2*)&bw);
                ax += wsel.x * vt.x + wsel.y * vb.x;
                ay += wsel.x * vt.y + wsel.y * vb.y;
            } else {
                int xc = (meta & 0xFF) - 4 + xsel;     // padded x of this corner
                int y0 = ((meta >> 8) & 0xFF) - 4;
                if (xc >= 1 && xc <= 64) {
                    const float* cb = xp + g * 32 + 2 * cp;
                    if (y0 >= 1 && y0 <= 64) {
                        const float* r = cb + (size_t)((y0 - 1) * 64 + xc - 1) * 128;
                        ax += wsel.x * r[0];
                        ay += wsel.x * r[1];
                    }
                    if (y0 >= 0 && y0 <= 63) {
                        const float* r = cb + (size_t)(y0 * 64 + xc - 1) * 128;
                        ax += wsel.y * r[0];
                        ay += wsel.y * r[1];
                    }
                }
            }
        }
        float ox = __shfl_down_sync(0xffffffffu, ax, 16);
        float oy = __shfl_down_sync(0xffffffffu, ay, 16);
        if (lane < 16) {
            int gpix = b * 4096 + (h0 + (pix >> 3)) * 64 + w0 + (pix & 7);
            float2 o;
            o.x = f2tf32f(ax + ox);
            o.y = f2tf32f(ay + oy);
            *(float2*)(g_samp + (size_t)gpix * 128 + g * 32 + 2 * cp) = o;
        }
    }
}

// ---------------------------------------------------------------------------
extern "C" void kernel_launch(void* const* d_in, const int* in_sizes, int n_in,
                              void* d_out, int out_size) {
    const float* x          = (const float*)d_in[0];
    const float* conv_w     = (const float*)d_in[1];
    const float* conv_b     = (const float*)d_in[2];
    const float* in_proj_w  = (const float*)d_in[3];
    const float* in_proj_b  = (const float*)d_in[4];
    const float* dw_w       = (const float*)d_in[5];
    const float* dw_b       = (const float*)d_in[6];
    const float* ln_g       = (const float*)d_in[7];
    const float* ln_b       = (const float*)d_in[8];
    const float* off_w      = (const float*)d_in[9];
    const float* off_b      = (const float*)d_in[10];
    const float* mask_w     = (const float*)d_in[11];
    const float* mask_b     = (const float*)d_in[12];
    const float* out_proj_w = (const float*)d_in[13];
    const float* out_proj_b = (const float*)d_in[14];
    float* out = (float*)d_out;

    float *dbuf, *samp, *bimg, *bcb, *om;
    cudaGetSymbolAddress((void**)&dbuf, g_d);
    cudaGetSymbolAddress((void**)&samp, g_samp);
    cudaGetSymbolAddress((void**)&bimg, g_Bimg);
    cudaGetSymbolAddress((void**)&bcb,  g_bcomb);
    cudaGetSymbolAddress((void**)&om,   g_om);

    cudaFuncSetAttribute(mma_gemm_async,  cudaFuncAttributeMaxDynamicSharedMemorySize, SMEM_BYTES);
    cudaFuncSetAttribute(fused_prep_nchw, cudaFuncAttributeMaxDynamicSharedMemorySize, SMEM_BYTES);
    cudaFuncSetAttribute(fused_inproj_dw, cudaFuncAttributeMaxDynamicSharedMemorySize, SMEM_BYTES);
    cudaFuncSetAttribute(dcn_core_tiled,  cudaFuncAttributeMaxDynamicSharedMemorySize, DCN_SMEM_BYTES);

    const int M1 = BB*HS*WS;   // 30752
    const int M2 = BB*HH*WW;   // 32768

    fused_prep_nchw<<<1441, 256, SMEM_BYTES>>>(x, conv_w, in_proj_w, off_w, off_b,
                                               mask_w, mask_b, out_proj_w, conv_b, M1);
    fused_inproj_dw<<<768, 256, SMEM_BYTES>>>(bimg + 16384, in_proj_b,
                                              dw_w, dw_b, ln_g, ln_b);
    mma_gemm_async<<<M2/128, 256, SMEM_BYTES>>>(dbuf, bimg + 2*16384, bcb, om,  M2, 0);
    dcn_core_tiled<<<2048, 256, DCN_SMEM_BYTES>>>();
    mma_gemm_async<<<M2/128, 256, SMEM_BYTES>>>(samp, bimg + 3*16384, out_proj_b, out, M2, 2);
}

// round 14
// speedup vs baseline: 1.0198x; 1.0198x over previous
#include <cuda_runtime.h>
#include <math.h>
#include <cstdint>

#define BB 8
#define CC 128
#define HS 62
#define WS 62
#define HH 64
#define WW 64
#define GG 4
#define PP 9

// ---------------------------------------------------------------------------
// Scratch
// ---------------------------------------------------------------------------
__device__ float g_y     [BB*HH*WW*CC];
__device__ float g_xproj [BB*HH*WW*CC];
__device__ float g_d     [BB*HH*WW*CC];
__device__ float g_om    [BB*HH*WW*CC];
__device__ float g_samp  [BB*HH*WW*CC];
__device__ float g_Bimg  [4*CC*CC];      // B fragment blobs (m=1..3 used), tf32
__device__ float g_bcomb [CC];

__device__ __forceinline__ uint32_t f2tf32(float f) {
    uint32_t u;
    asm("cvt.rna.tf32.f32 %0, %1;" : "=r"(u) : "f"(f));
    return u;
}
__device__ __forceinline__ float f2tf32f(float f) {
    return __uint_as_float(f2tf32(f));
}
__device__ __forceinline__ uint32_t s2u(const void* p) {
    return (uint32_t)__cvta_generic_to_shared(p);
}
__device__ __forceinline__ void cp_async16(uint32_t dst, const void* src) {
    asm volatile("cp.async.cg.shared.global [%0], [%1], 16;" :: "r"(dst), "l"(src));
}
__device__ __forceinline__ void cp_async16_z(uint32_t dst, const void* src, int vsize) {
    asm volatile("cp.async.cg.shared.global [%0], [%1], 16, %2;"
                 :: "r"(dst), "l"(src), "r"(vsize));
}
#define CP_COMMIT() asm volatile("cp.async.commit_group;" ::: "memory")
#define CP_WAIT(n)  asm volatile("cp.async.wait_group %0;" :: "n"(n) : "memory")

// ---------------------------------------------------------------------------
// Shared GEMM geometry. B blob: 16384 floats, no padding.
// ---------------------------------------------------------------------------
#define ASTR 36
#define CSTR 132
#define OFF_B 0
#define OFF_A0 16384
#define OFF_A1 (16384 + 128*ASTR)
#define OFF_BIAS (16384 + 2*128*ASTR)
#define SMEM_FLOATS (16384 + 2*128*ASTR + 128)
#define SMEM_BYTES (SMEM_FLOATS * 4)

#define DECL_ACC                                                              \
    float acc[2][8][4];                                                       \
    _Pragma("unroll") for (int i = 0; i < 2; i++)                             \
    _Pragma("unroll") for (int j = 0; j < 8; j++)                             \
    _Pragma("unroll") for (int q = 0; q < 4; q++) acc[i][j][q] = 0.f;

#define COMPUTE_CHUNK(kc)                                                     \
do {                                                                          \
    const float* As = smem + (((kc) & 1) ? OFF_A1 : OFF_A0);                  \
    _Pragma("unroll")                                                         \
    for (int ks = 0; ks < 4; ks++) {                                          \
        int k0 = ks * 8;                                                      \
        uint32_t a[2][4];                                                     \
        _Pragma("unroll")                                                     \
        for (int rg = 0; rg < 2; rg++) {                                      \
            const float* ab = As + (wr * 32 + rg * 16 + lg) * ASTR + k0 + lk; \
            a[rg][0] = __float_as_uint(ab[0]);                                \
            a[rg][1] = __float_as_uint(ab[8 * ASTR]);                         \
            a[rg][2] = __float_as_uint(ab[4]);                                \
            a[rg][3] = __float_as_uint(ab[8 * ASTR + 4]);                     \
        }                                                                     \
        const float4* bb = (const float4*)(smem + OFF_B)                      \
                         + (((wc * 16 + (kc) * 4 + ks) * 4) * 32 + lane);     \
        float4 q0 = bb[0], q1 = bb[32], q2 = bb[64], q3 = bb[96];             \
        uint32_t bfr[8][2];                                                   \
        bfr[0][0] = __float_as_uint(q0.x); bfr[0][1] = __float_as_uint(q0.y); \
        bfr[1][0] = __float_as_uint(q0.z); bfr[1][1] = __float_as_uint(q0.w); \
        bfr[2][0] = __float_as_uint(q1.x); bfr[2][1] = __float_as_uint(q1.y); \
        bfr[3][0] = __float_as_uint(q1.z); bfr[3][1] = __float_as_uint(q1.w); \
        bfr[4][0] = __float_as_uint(q2.x); bfr[4][1] = __float_as_uint(q2.y); \
        bfr[5][0] = __float_as_uint(q2.z); bfr[5][1] = __float_as_uint(q2.w); \
        bfr[6][0] = __float_as_uint(q3.x); bfr[6][1] = __float_as_uint(q3.y); \
        bfr[7][0] = __float_as_uint(q3.z); bfr[7][1] = __float_as_uint(q3.w); \
        _Pragma("unroll")                                                     \
        for (int rg = 0; rg < 2; rg++)                                        \
        _Pragma("unroll")                                                     \
        for (int nf = 0; nf < 8; nf++) {                                      \
            asm volatile(                                                     \
                "mma.sync.aligned.m16n8k8.row.col.f32.tf32.tf32.f32 "         \
                "{%0,%1,%2,%3}, {%4,%5,%6,%7}, {%8,%9}, {%0,%1,%2,%3};"       \
                : "+f"(acc[rg][nf][0]), "+f"(acc[rg][nf][1]),                 \
                  "+f"(acc[rg][nf][2]), "+f"(acc[rg][nf][3])                  \
                : "r"(a[rg][0]), "r"(a[rg][1]), "r"(a[rg][2]), "r"(a[rg][3]), \
                  "r"(bfr[nf][0]), "r"(bfr[nf][1]));                          \
        }                                                                     \
    }                                                                         \
} while (0)

#define ISSUE_A(ck, buf)                                                      \
do {                                                                          \
    float* As_ = smem + ((buf) ? OFF_A1 : OFF_A0);                            \
    int k0_ = (ck) * 32;                                                      \
    _Pragma("unroll")                                                         \
    for (int j = 0; j < 4; j++) {                                             \
        int f4 = tid + j * 256;                                               \
        int r = f4 >> 3, kq = (f4 & 7) * 4;                                   \
        cp_async16(s2u(As_ + r * ASTR + kq),                                  \
                   A + (size_t)(row0 + r) * 128 + k0_ + kq);                  \
    }                                                                         \
} while (0)

// Core async GEMM body (A tf32-pre-rounded, M mult of 128)
__device__ __forceinline__ void gemm_body(
        float* smem, const float* __restrict__ A, const float* __restrict__ Bimg,
        const float* __restrict__ bias, float* __restrict__ Cmat,
        int row0, int mode) {
    float* sbias = smem + OFF_BIAS;
    int tid = threadIdx.x;
    int lane = tid & 31;
    int wid = tid >> 5;

    if (tid < 128) sbias[tid] = bias[tid];

#pragma unroll
    for (int j = 0; j < 16; j++) {
        int f4 = tid + j * 256;
        cp_async16(s2u(smem + OFF_B + f4 * 4), Bimg + f4 * 4);
    }
    ISSUE_A(0, 0);
    CP_COMMIT();
    ISSUE_A(1, 1);
    CP_COMMIT();
    CP_WAIT(1);
    __syncthreads();

    int wr = wid >> 1;
    int wc = wid & 1;
    int lg = lane >> 2;
    int lk = lane & 3;
    DECL_ACC;

#pragma unroll
    for (int kc = 0; kc < 4; kc++) {
        COMPUTE_CHUNK(kc);
        if (kc < 3) {
            __syncthreads();
            if (kc < 2) {
                ISSUE_A(kc + 2, kc & 1);
                CP_COMMIT();
                CP_WAIT(1);
            } else {
                CP_WAIT(0);
            }
            __syncthreads();
        }
    }

    if (mode == 2) {
        __syncthreads();
        float* Cs = smem;
#pragma unroll
        for (int rg = 0; rg < 2; rg++)
#pragma unroll
            for (int half = 0; half < 2; half++) {
                int r = wr * 32 + rg * 16 + lg + half * 8;
#pragma unroll
                for (int nf = 0; nf < 8; nf++) {
                    int col = wc * 64 + nf * 8 + 2 * lk;
                    Cs[col * CSTR + r]       = acc[rg][nf][half * 2 + 0] + sbias[col];
                    Cs[(col + 1) * CSTR + r] = acc[rg][nf][half * 2 + 1] + sbias[col + 1];
                }
            }
        __syncthreads();
        int bimg2 = row0 >> 12;
        int pix0 = row0 & 4095;
#pragma unroll
        for (int j = 0; j < 16; j++) {
            int f4 = tid + j * 256;
            int ch = f4 >> 5, p4 = (f4 & 31) * 4;
            float4 v = *(const float4*)(Cs + ch * CSTR + p4);
            *(float4*)(Cmat + (size_t)(bimg2 * 128 + ch) * 4096 + pix0 + p4) = v;
        }
        return;
    }

#pragma unroll
    for (int rg = 0; rg < 2; rg++)
#pragma unroll
        for (int half = 0; half < 2; half++) {
            int row = row0 + wr * 32 + rg * 16 + lg + half * 8;
            float* cr = Cmat + (size_t)row * 128;
#pragma unroll
            for (int nf = 0; nf < 8; nf++) {
                int col = wc * 64 + nf * 8 + 2 * lk;
                float2 o;
                o.x = acc[rg][nf][half * 2 + 0] + sbias[col];
                o.y = acc[rg][nf][half * 2 + 1] + sbias[col + 1];
                *(float2*)(cr + col) = o;
            }
        }
}

__global__ __launch_bounds__(256, 2) void mma_gemm_async(
        const float* __restrict__ A, const float* __restrict__ Bimg,
        const float* __restrict__ bias, float* __restrict__ Cmat,
        int M, int mode) {
    extern __shared__ float smem[];
    gemm_body(smem, A, Bimg, bias, Cmat, blockIdx.x * 128, mode);
    (void)M;
}

// ---------------------------------------------------------------------------
// Fused stage 1: blocks 0..240 -> GEMM1 (NCHW x -> y interior);
// blocks 241..432 -> B blobs m=1..3; blocks 433..1440 -> border ring of y.
// ---------------------------------------------------------------------------
__global__ __launch_bounds__(256, 2) void fused_prep_nchw(
        const float* __restrict__ A, const float* __restrict__ conv_w,
        const float* __restrict__ in_proj_w,
        const float* __restrict__ off_w, const float* __restrict__ off_b,
        const float* __restrict__ mask_w, const float* __restrict__ mask_b,
        const float* __restrict__ out_proj_w,
        const float* __restrict__ conv_b, int M) {
    extern __shared__ float smem[];
    int tid = threadIdx.x;
    int blk = blockIdx.x;

    if (blk >= 241) {
        if (blk < 433) {
            int m = 1 + ((blk - 241) >> 6);
            int inner = (blk - 241) & 63;
            int idx = m * 16384 + inner * 256 + tid;
            int f = idx & 16383;
            int f4 = f >> 2, comp = f & 3;
            int lane_ = f4 & 31;
            int t = f4 >> 5;
            int q = t & 3; t >>= 2;
            int ks = t & 15;
            int wcx = t >> 4;
            int nf = 2 * q + (comp >> 1);
            int n = wcx * 64 + nf * 8 + (lane_ >> 2);
            int k = ks * 8 + (lane_ & 3) + ((comp & 1) << 2);
            float v = 0.f;
            if (m == 1) v = in_proj_w[k * CC + n];
            else if (m == 2) {
                if (n < 72)       v = off_w[k * 72 + n];
                else if (n < 108) v = mask_w[k * 36 + (n - 72)];
            } else v = out_proj_w[k * CC + n];
            ((uint32_t*)g_Bimg)[idx] = f2tf32(v);
            if (blk == 241 && tid < CC)
                g_bcomb[tid] = (tid < 72) ? off_b[tid]
                             : (tid < 108 ? mask_b[tid - 72] : 0.f);
        } else {
            int idx = (blk - 433) * 256 + tid;
            int b = idx / (252 * 128);
            int r = idx - b * (252 * 128);
            int pi = r >> 7, c = r & 127;
            int h, w;
            if (pi < 64)       { h = 0;        w = pi; }
            else if (pi < 128) { h = 63;       w = pi - 64; }
            else if (pi < 190) { h = pi - 127; w = 0; }
            else               { h = pi - 189; w = 63; }
            g_y[((size_t)(b * 4096 + h * 64 + w)) * 128 + c] = f2tf32f(conv_b[c]);
        }
        return;
    }

    // ---- NCHW GEMM tile ----
    float* sbias = smem + OFF_BIAS;
    int lane = tid & 31;
    int wid = tid >> 5;
    int row0 = blk * 128;

    if (tid < 128) sbias[tid] = conv_b[tid];

#pragma unroll
    for (int j = 0; j < 16; j++) {
        int f4i = tid + j * 256;
        int lane_ = f4i & 31;
        int t = f4i >> 5;
        int q = t & 3; t >>= 2;
        int ks = t & 15;
        int wcx = t >> 4;
        int lg_ = lane_ >> 2, lk_ = lane_ & 3;
        int n0 = wcx * 64 + (2 * q) * 8 + lg_;
        int n1 = n0 + 8;
        int k0 = ks * 8 + lk_;
        uint4 u;
        u.x = f2tf32(conv_w[n0 * 128 + k0]);
        u.y = f2tf32(conv_w[n0 * 128 + k0 + 4]);
        u.z = f2tf32(conv_w[n1 * 128 + k0]);
        u.w = f2tf32(conv_w[n1 * 128 + k0 + 4]);
        *(uint4*)(smem + OFF_B + f4i * 4) = u;
    }

    float rstage[16];
#define PREFETCH1(kc)                                                         \
do {                                                                          \
    int k0 = (kc) * 32;                                                       \
    _Pragma("unroll")                                                         \
    for (int j = 0; j < 16; j++) {                                            \
        int idx = tid + j * 256;                                              \
        int r = idx & 127, cl = idx >> 7;                                     \
        int grow = row0 + r; if (grow >= M) grow = M - 1;                     \
        int b = grow / 3844;                                                  \
        int s = grow - b * 3844;                                              \
        rstage[j] = A[(size_t)(b * 128 + k0 + cl) * 3844 + s];                \
    }                                                                         \
} while (0)
#define STORE1(buf)                                                           \
do {                                                                          \
    float* As_ = smem + ((buf) ? OFF_A1 : OFF_A0);                            \
    _Pragma("unroll")                                                         \
    for (int j = 0; j < 16; j++) {                                            \
        int idx = tid + j * 256;                                              \
        int r = idx & 127, cl = idx >> 7;                                     \
        ((uint32_t*)(As_ + r * ASTR + cl))[0] = f2tf32(rstage[j]);            \
    }                                                                         \
} while (0)

    PREFETCH1(0);
    STORE1(0);
    __syncthreads();

    int wr = wid >> 1;
    int wc = wid & 1;
    int lg = lane >> 2;
    int lk = lane & 3;
    DECL_ACC;

#pragma unroll
    for (int kc = 0; kc < 4; kc++) {
        if (kc < 3) PREFETCH1(kc + 1);
        COMPUTE_CHUNK(kc);
        if (kc < 3) {
            STORE1((kc + 1) & 1);
            __syncthreads();
        }
    }

#pragma unroll
    for (int rg = 0; rg < 2; rg++)
#pragma unroll
        for (int half = 0; half < 2; half++) {
            int row = row0 + wr * 32 + rg * 16 + lg + half * 8;
            if (row < M) {
                int b2 = row / 3844;
                int r = row - b2 * 3844;
                int hh = r / 62;
                int ww2 = r - hh * 62;
                float* cr = g_y + ((size_t)(b2 * 4096 + (hh + 1) * 64 + ww2 + 1)) * 128;
#pragma unroll
                for (int nf = 0; nf < 8; nf++) {
                    int col = wc * 64 + nf * 8 + 2 * lk;
                    float2 o;
                    o.x = f2tf32f(acc[rg][nf][half * 2 + 0] + sbias[col]);
                    o.y = f2tf32f(acc[rg][nf][half * 2 + 1] + sbias[col + 1]);
                    *(float2*)(cr + col) = o;
                }
            }
        }
#undef PREFETCH1
#undef STORE1
}

// ---------------------------------------------------------------------------
// dw body (tiled): blk in [0,512), 8x8 pixel tile, patch 10x10x128
// ---------------------------------------------------------------------------
__device__ __forceinline__ void dw_body(
        float* patch, int blk,
        const float* __restrict__ dw_w, const float* __restrict__ dw_b,
        const float* __restrict__ ln_g, const float* __restrict__ ln_b) {
    int b = blk >> 6;
    int tile = blk & 63;
    int h0 = (tile >> 3) * 8, w0 = (tile & 7) * 8;
    int tid = threadIdx.x;
    int lane = tid & 31;
    int warp = tid >> 5;

#pragma unroll
    for (int j = 0; j < 13; j++) {
        int idx = tid + j * 256;
        if (idx < 3200) {
            int pos = idx >> 5, q = idx & 31;
            int py = pos / 10, px = pos - py * 10;
            int hh = h0 - 1 + py, ww = w0 - 1 + px;
            bool valid = ((unsigned)hh < 64u) && ((unsigned)ww < 64u);
            int hc = valid ? hh : 0, wc2 = valid ? ww : 0;
            cp_async16_z(s2u(patch + pos * 128 + q * 4),
                         g_y + ((size_t)(b * 4096 + hc * 64 + wc2)) * 128 + q * 4,
                         valid ? 16 : 0);
        }
    }
    CP_COMMIT();

    int c0 = lane * 4;
    float4 wv[9];
#pragma unroll
    for (int t = 0; t < 9; t++) {
        wv[t].x = dw_w[(c0 + 0) * 9 + t];
        wv[t].y = dw_w[(c0 + 1) * 9 + t];
        wv[t].z = dw_w[(c0 + 2) * 9 + t];
        wv[t].w = dw_w[(c0 + 3) * 9 + t];
    }
    float4 bv = *(const float4*)(dw_b + c0);
    float4 gv = *(const float4*)(ln_g + c0);
    float4 lbv = *(const float4*)(ln_b + c0);

    CP_WAIT(0);
    __syncthreads();

#pragma unroll
    for (int i = 0; i < 8; i++) {
        int pix = warp * 8 + i;
        int py = pix >> 3, px = pix & 7;
        float4 acc = bv;
#pragma unroll
        for (int kh = 0; kh < 3; kh++)
#pragma unroll
            for (int kw = 0; kw < 3; kw++) {
                float4 v = *(const float4*)(patch + ((py + kh) * 10 + (px + kw)) * 128 + c0);
                acc.x += v.x * wv[kh * 3 + kw].x;
                acc.y += v.y * wv[kh * 3 + kw].y;
                acc.z += v.z * wv[kh * 3 + kw].z;
                acc.w += v.w * wv[kh * 3 + kw].w;
            }
        float s  = acc.x + acc.y + acc.z + acc.w;
        float s2 = acc.x * acc.x + acc.y * acc.y + acc.z * acc.z + acc.w * acc.w;
#pragma unroll
        for (int o = 16; o; o >>= 1) {
            s  += __shfl_xor_sync(0xffffffffu, s,  o);
            s2 += __shfl_xor_sync(0xffffffffu, s2, o);
        }
        float mu  = s * (1.f / 128.f);
        float var = s2 * (1.f / 128.f) - mu * mu;
        float rstd = rsqrtf(var + 1e-5f);
        float4 o4;
        float v0 = (acc.x - mu) * rstd * gv.x + lbv.x;
        float v1 = (acc.y - mu) * rstd * gv.y + lbv.y;
        float v2 = (acc.z - mu) * rstd * gv.z + lbv.z;
        float v3 = (acc.w - mu) * rstd * gv.w + lbv.w;
        o4.x = f2tf32f(0.5f * v0 * (1.f + erff(v0 * 0.70710678118654752440f)));
        o4.y = f2tf32f(0.5f * v1 * (1.f + erff(v1 * 0.70710678118654752440f)));
        o4.z = f2tf32f(0.5f * v2 * (1.f + erff(v2 * 0.70710678118654752440f)));
        o4.w = f2tf32f(0.5f * v3 * (1.f + erff(v3 * 0.70710678118654752440f)));
        size_t gp = (size_t)(b * 4096 + (h0 + py) * 64 + (w0 + px)) * 128 + c0;
        *(float4*)(g_d + gp) = o4;
    }
}

// ---------------------------------------------------------------------------
// Fused stage 2: blocks 0..255 -> in_proj GEMM (y->xproj);
//                blocks 256..767 -> dw+LN+GELU (y->d).
// ---------------------------------------------------------------------------
__global__ __launch_bounds__(256, 2) void fused_inproj_dw(
        const float* __restrict__ Bimg, const float* __restrict__ in_proj_b,
        const float* __restrict__ dw_w, const float* __restrict__ dw_b,
        const float* __restrict__ ln_g, const float* __restrict__ ln_b) {
    extern __shared__ float smem[];
    if (blockIdx.x < 256) {
        gemm_body(smem, g_y, Bimg, in_proj_b, g_xproj, blockIdx.x * 128, 0);
    } else {
        dw_body(smem, blockIdx.x - 256, dw_w, dw_b, ln_g, ln_b);
    }
}

// ---------------------------------------------------------------------------
// Tiled DCNv3 core (R12 version): block = (tile, group). 2048 blocks,
// 14x14 halo-3 f32 patch. smem = 38,912 B -> 5 CTAs/SM.
// ---------------------------------------------------------------------------
#define DCN_PATCH_OFF 0
#define DCN_MASK_OFF  6272
#define DCN_PLANW_OFF (6272 + 576)
#define DCN_PLANM_OFF (6272 + 576 + 2304)
#define DCN_SMEM_FLOATS (6272 + 576 + 2304 + 576)
#define DCN_SMEM_BYTES (DCN_SMEM_FLOATS * 4)

__global__ __launch_bounds__(256, 5) void dcn_core_tiled() {
    extern __shared__ float smem[];
    float* patch = smem + DCN_PATCH_OFF;             // [196][32]
    float* smask = smem + DCN_MASK_OFF;              // [64][9]
    float4* planw = (float4*)(smem + DCN_PLANW_OFF); // [576]
    int*    planm = (int*)(smem + DCN_PLANM_OFF);    // [576]
    int blk = blockIdx.x;
    int g = blk & 3;
    int tileid = blk >> 2;
    int b = tileid >> 6;
    int tile = tileid & 63;
    int h0 = (tile >> 3) * 8, w0 = (tile & 7) * 8;
    int tid = threadIdx.x;
    int lane = tid & 31;
    int warp = tid >> 5;
    const float* xp = g_xproj + (size_t)b * 4096 * 128;
    const float* omb = g_om + (size_t)b * 4096 * 128;

    // patch: 196 positions x 8 float4 (32 ch), halo 3
#pragma unroll
    for (int j = 0; j < 7; j++) {
        int idx = tid + j * 256;
        if (idx < 1568) {
            int pos = idx >> 3, q = idx & 7;
            int py = pos / 14, px = pos - py * 14;
            int iy = h0 - 3 + py, ix = w0 - 3 + px;
            bool valid = ((unsigned)iy < 64u) && ((unsigned)ix < 64u);
            int yc = valid ? iy : 0, xc = valid ? ix : 0;
            cp_async16_z(s2u(patch + pos * 32 + q * 4),
                         xp + ((size_t)(yc * 64 + xc)) * 128 + g * 32 + q * 4,
                         valid ? 16 : 0);
        }
    }
    CP_COMMIT();

    // softmax for this group's mask: thread = pixel (direct global reads)
    if (tid < 64) {
        int lpix = (h0 + (tid >> 3)) * 64 + w0 + (tid & 7);
        const float* mp = omb + (size_t)lpix * 128 + 72 + g * 9;
        float v[9];
        float mx = -1e30f;
#pragma unroll
        for (int i = 0; i < 9; i++) { v[i] = mp[i]; mx = fmaxf(mx, v[i]); }
        float sum = 0.f;
#pragma unroll
        for (int i = 0; i < 9; i++) { v[i] = expf(v[i] - mx); sum += v[i]; }
        float inv = 1.f / sum;
#pragma unroll
        for (int i = 0; i < 9; i++) smask[tid * 9 + i] = v[i] * inv;
    }
    __syncthreads();

    // plan: 576 items = (pix, p); offsets read directly from global
#pragma unroll
    for (int j = 0; j < 3; j++) {
        int item = tid + j * 256;
        if (item < 576) {
            int pix = item / 9, p = item - pix * 9;
            int w = w0 + (pix & 7), h = h0 + (pix >> 3);
            int lpix = h * 64 + w;
            float2 off = *(const float2*)(omb + (size_t)lpix * 128 + (g * 9 + p) * 2);
            float mv = smask[pix * 9 + p];
            float ix = (float)(w + (p / 3)) + off.x;
            float iy = (float)(h + (p % 3)) + off.y;
            float x0f = floorf(ix), y0f = floorf(iy);
            int x0 = (int)x0f, y0 = (int)y0f;
            float fx = ix - x0f, fy = iy - y0f;
            float wx0 = 1.f - fx, wy0 = 1.f - fy;
            float4 wt;
            wt.x = mv * wx0 * wy0;
            wt.y = mv * fx  * wy0;
            wt.z = mv * wx0 * fy;
            wt.w = mv * fx  * fy;
            planw[item] = wt;
            int px0 = x0 - w0 + 2, py0 = y0 - h0 + 2;
            int meta;
            if ((unsigned)px0 <= 12u && (unsigned)py0 <= 12u) {
                meta = (py0 * 14 + px0) * 32;
            } else {
                int x0c = min(max(x0, -4), 68) + 4;
                int y0c = min(max(y0, -4), 68) + 4;
                meta = (int)(0x80000000u | (unsigned)(y0c << 8) | (unsigned)x0c);
            }
            planm[item] = meta;
        }
    }
    CP_WAIT(0);
    __syncthreads();

    // gather: warp -> 8 pixels, lane -> channel within group
#pragma unroll
    for (int i = 0; i < 8; i++) {
        int pix = warp * 8 + i;
        float acc = 0.f;
#pragma unroll
        for (int p = 0; p < 9; p++) {
            int item = pix * 9 + p;
            float4 wt = planw[item];
            int meta = planm[item];
            if (meta >= 0) {
                const float* pb = patch + meta + lane;
                acc += wt.x * pb[0];
                acc += wt.y * pb[32];
                acc += wt.z * pb[448];
                acc += wt.w * pb[480];
            } else {
                int x0 = (meta & 0xFF) - 4;
                int y0 = ((meta >> 8) & 0xFF) - 4;
                const float* base = xp + g * 32 + lane;
                if (y0 >= 1 && y0 <= 64) {
                    const float* r = base + (size_t)((y0 - 1) * 64) * 128;
                    if (x0 >= 1 && x0 <= 64) acc += wt.x * r[(size_t)(x0 - 1) * 128];
                    if (x0 >= 0 && x0 <= 63) acc += wt.y * r[(size_t)x0 * 128];
                }
                if (y0 >= 0 && y0 <= 63) {
                    const float* r = base + (size_t)(y0 * 64) * 128;
                    if (x0 >= 1 && x0 <= 64) acc += wt.z * r[(size_t)(x0 - 1) * 128];
                    if (x0 >= 0 && x0 <= 63) acc += wt.w * r[(size_t)x0 * 128];
                }
            }
        }
        int gpix = b * 4096 + (h0 + (pix >> 3)) * 64 + w0 + (pix & 7);
        g_samp[(size_t)gpix * 128 + g * 32 + lane] = f2tf32f(acc);
    }
}

// ---------------------------------------------------------------------------
extern "C" void kernel_launch(void* const* d_in, const int* in_sizes, int n_in,
                              void* d_out, int out_size) {
    const float* x          = (const float*)d_in[0];
    const float* conv_w     = (const float*)d_in[1];
    const float* conv_b     = (const float*)d_in[2];
    const float* in_proj_w  = (const float*)d_in[3];
    const float* in_proj_b  = (const float*)d_in[4];
    const float* dw_w       = (const float*)d_in[5];
    const float* dw_b       = (const float*)d_in[6];
    const float* ln_g       = (const float*)d_in[7];
    const float* ln_b       = (const float*)d_in[8];
    const float* off_w      = (const float*)d_in[9];
    const float* off_b      = (const float*)d_in[10];
    const float* mask_w     = (const float*)d_in[11];
    const float* mask_b     = (const float*)d_in[12];
    const float* out_proj_w = (const float*)d_in[13];
    const float* out_proj_b = (const float*)d_in[14];
    float* out = (float*)d_out;

    float *dbuf, *samp, *bimg, *bcb, *om;
    cudaGetSymbolAddress((void**)&dbuf, g_d);
    cudaGetSymbolAddress((void**)&samp, g_samp);
    cudaGetSymbolAddress((void**)&bimg, g_Bimg);
    cudaGetSymbolAddress((void**)&bcb,  g_bcomb);
    cudaGetSymbolAddress((void**)&om,   g_om);

    cudaFuncSetAttribute(mma_gemm_async,  cudaFuncAttributeMaxDynamicSharedMemorySize, SMEM_BYTES);
    cudaFuncSetAttribute(fused_prep_nchw, cudaFuncAttributeMaxDynamicSharedMemorySize, SMEM_BYTES);
    cudaFuncSetAttribute(fused_inproj_dw, cudaFuncAttributeMaxDynamicSharedMemorySize, SMEM_BYTES);
    cudaFuncSetAttribute(dcn_core_tiled,  cudaFuncAttributeMaxDynamicSharedMemorySize, DCN_SMEM_BYTES);

    const int M1 = BB*HS*WS;   // 30752
    const int M2 = BB*HH*WW;   // 32768

    fused_prep_nchw<<<1441, 256, SMEM_BYTES>>>(x, conv_w, in_proj_w, off_w, off_b,
                                               mask_w, mask_b, out_proj_w, conv_b, M1);
    fused_inproj_dw<<<768, 256, SMEM_BYTES>>>(bimg + 16384, in_proj_b,
                                              dw_w, dw_b, ln_g, ln_b);
    mma_gemm_async<<<M2/128, 256, SMEM_BYTES>>>(dbuf, bimg + 2*16384, bcb, om,  M2, 0);
    dcn_core_tiled<<<2048, 256, DCN_SMEM_BYTES>>>();
    mma_gemm_async<<<M2/128, 256, SMEM_BYTES>>>(samp, bimg + 3*16384, out_proj_b, out, M2, 2);
}

// round 15
// speedup vs baseline: 1.0613x; 1.0407x over previous
#include <cuda_runtime.h>
#include <math.h>
#include <cstdint>

#define BB 8
#define CC 128
#define HS 62
#define WS 62
#define HH 64
#define WW 64
#define GG 4
#define PP 9

// ---------------------------------------------------------------------------
// Scratch
// ---------------------------------------------------------------------------
__device__ float g_y     [BB*HH*WW*CC];
__device__ float g_xproj [BB*HH*WW*CC];
__device__ float g_d     [BB*HH*WW*CC];
__device__ float g_om    [BB*HH*WW*CC];
__device__ float g_samp  [BB*HH*WW*CC];
__device__ float g_Bimg  [4*CC*CC];      // B fragment blobs (m=1..3 used), tf32
__device__ float g_bcomb [CC];

__device__ __forceinline__ uint32_t f2tf32(float f) {
    uint32_t u;
    asm("cvt.rna.tf32.f32 %0, %1;" : "=r"(u) : "f"(f));
    return u;
}
__device__ __forceinline__ float f2tf32f(float f) {
    return __uint_as_float(f2tf32(f));
}
__device__ __forceinline__ uint32_t s2u(const void* p) {
    return (uint32_t)__cvta_generic_to_shared(p);
}
__device__ __forceinline__ void cp_async16(uint32_t dst, const void* src) {
    asm volatile("cp.async.cg.shared.global [%0], [%1], 16;" :: "r"(dst), "l"(src));
}
__device__ __forceinline__ void cp_async16_z(uint32_t dst, const void* src, int vsize) {
    asm volatile("cp.async.cg.shared.global [%0], [%1], 16, %2;"
                 :: "r"(dst), "l"(src), "r"(vsize));
}
#define CP_COMMIT() asm volatile("cp.async.commit_group;" ::: "memory")
#define CP_WAIT(n)  asm volatile("cp.async.wait_group %0;" :: "n"(n) : "memory")
// Programmatic dependent launch controls (sm_90+ baseline)
#define GDC_WAIT()   asm volatile("griddepcontrol.wait;" ::: "memory")
#define GDC_LAUNCH() asm volatile("griddepcontrol.launch_dependents;" ::: "memory")

// ---------------------------------------------------------------------------
// Shared GEMM geometry. B blob: 16384 floats, no padding.
// ---------------------------------------------------------------------------
#define ASTR 36
#define CSTR 132
#define OFF_B 0
#define OFF_A0 16384
#define OFF_A1 (16384 + 128*ASTR)
#define OFF_BIAS (16384 + 2*128*ASTR)
#define SMEM_FLOATS (16384 + 2*128*ASTR + 128)
#define SMEM_BYTES (SMEM_FLOATS * 4)

#define DECL_ACC                                                              \
    float acc[2][8][4];                                                       \
    _Pragma("unroll") for (int i = 0; i < 2; i++)                             \
    _Pragma("unroll") for (int j = 0; j < 8; j++)                             \
    _Pragma("unroll") for (int q = 0; q < 4; q++) acc[i][j][q] = 0.f;

#define COMPUTE_CHUNK(kc)                                                     \
do {                                                                          \
    const float* As = smem + (((kc) & 1) ? OFF_A1 : OFF_A0);                  \
    _Pragma("unroll")                                                         \
    for (int ks = 0; ks < 4; ks++) {                                          \
        int k0 = ks * 8;                                                      \
        uint32_t a[2][4];                                                     \
        _Pragma("unroll")                                                     \
        for (int rg = 0; rg < 2; rg++) {                                      \
            const float* ab = As + (wr * 32 + rg * 16 + lg) * ASTR + k0 + lk; \
            a[rg][0] = __float_as_uint(ab[0]);                                \
            a[rg][1] = __float_as_uint(ab[8 * ASTR]);                         \
            a[rg][2] = __float_as_uint(ab[4]);                                \
            a[rg][3] = __float_as_uint(ab[8 * ASTR + 4]);                     \
        }                                                                     \
        const float4* bb = (const float4*)(smem + OFF_B)                      \
                         + (((wc * 16 + (kc) * 4 + ks) * 4) * 32 + lane);     \
        float4 q0 = bb[0], q1 = bb[32], q2 = bb[64], q3 = bb[96];             \
        uint32_t bfr[8][2];                                                   \
        bfr[0][0] = __float_as_uint(q0.x); bfr[0][1] = __float_as_uint(q0.y); \
        bfr[1][0] = __float_as_uint(q0.z); bfr[1][1] = __float_as_uint(q0.w); \
        bfr[2][0] = __float_as_uint(q1.x); bfr[2][1] = __float_as_uint(q1.y); \
        bfr[3][0] = __float_as_uint(q1.z); bfr[3][1] = __float_as_uint(q1.w); \
        bfr[4][0] = __float_as_uint(q2.x); bfr[4][1] = __float_as_uint(q2.y); \
        bfr[5][0] = __float_as_uint(q2.z); bfr[5][1] = __float_as_uint(q2.w); \
        bfr[6][0] = __float_as_uint(q3.x); bfr[6][1] = __float_as_uint(q3.y); \
        bfr[7][0] = __float_as_uint(q3.z); bfr[7][1] = __float_as_uint(q3.w); \
        _Pragma("unroll")                                                     \
        for (int rg = 0; rg < 2; rg++)                                        \
        _Pragma("unroll")                                                     \
        for (int nf = 0; nf < 8; nf++) {                                      \
            asm volatile(                                                     \
                "mma.sync.aligned.m16n8k8.row.col.f32.tf32.tf32.f32 "         \
                "{%0,%1,%2,%3}, {%4,%5,%6,%7}, {%8,%9}, {%0,%1,%2,%3};"       \
                : "+f"(acc[rg][nf][0]), "+f"(acc[rg][nf][1]),                 \
                  "+f"(acc[rg][nf][2]), "+f"(acc[rg][nf][3])                  \
                : "r"(a[rg][0]), "r"(a[rg][1]), "r"(a[rg][2]), "r"(a[rg][3]), \
                  "r"(bfr[nf][0]), "r"(bfr[nf][1]));                          \
        }                                                                     \
    }                                                                         \
} while (0)

#define ISSUE_A(ck, buf)                                                      \
do {                                                                          \
    float* As_ = smem + ((buf) ? OFF_A1 : OFF_A0);                            \
    int k0_ = (ck) * 32;                                                      \
    _Pragma("unroll")                                                         \
    for (int j = 0; j < 4; j++) {                                             \
        int f4 = tid + j * 256;                                               \
        int r = f4 >> 3, kq = (f4 & 7) * 4;                                   \
        cp_async16(s2u(As_ + r * ASTR + kq),                                  \
                   A + (size_t)(row0 + r) * 128 + k0_ + kq);                  \
    }                                                                         \
} while (0)

// Core async GEMM body (A tf32-pre-rounded, M mult of 128)
// pdl: 0 = everything dependent (wait already done by caller)
//      1 = B blob independent: load B, then GDC wait+trigger, then A.
__device__ __forceinline__ void gemm_body(
        float* smem, const float* __restrict__ A, const float* __restrict__ Bimg,
        const float* __restrict__ bias, float* __restrict__ Cmat,
        int row0, int mode, int pdl) {
    float* sbias = smem + OFF_BIAS;
    int tid = threadIdx.x;
    int lane = tid & 31;
    int wid = tid >> 5;

    if (tid < 128) sbias[tid] = bias[tid];

#pragma unroll
    for (int j = 0; j < 16; j++) {
        int f4 = tid + j * 256;
        cp_async16(s2u(smem + OFF_B + f4 * 4), Bimg + f4 * 4);
    }
    if (pdl) {
        CP_COMMIT();          // group: B
        GDC_WAIT();
        GDC_LAUNCH();
        ISSUE_A(0, 0);
        CP_COMMIT();          // group: A0
        ISSUE_A(1, 1);
        CP_COMMIT();          // group: A1
        CP_WAIT(1);           // B + A0 resident
    } else {
        ISSUE_A(0, 0);
        CP_COMMIT();
        ISSUE_A(1, 1);
        CP_COMMIT();
        CP_WAIT(1);
    }
    __syncthreads();

    int wr = wid >> 1;
    int wc = wid & 1;
    int lg = lane >> 2;
    int lk = lane & 3;
    DECL_ACC;

#pragma unroll
    for (int kc = 0; kc < 4; kc++) {
        COMPUTE_CHUNK(kc);
        if (kc < 3) {
            __syncthreads();
            if (kc < 2) {
                ISSUE_A(kc + 2, kc & 1);
                CP_COMMIT();
                CP_WAIT(1);
            } else {
                CP_WAIT(0);
            }
            __syncthreads();
        }
    }

    if (mode == 2) {
        __syncthreads();
        float* Cs = smem;
#pragma unroll
        for (int rg = 0; rg < 2; rg++)
#pragma unroll
            for (int half = 0; half < 2; half++) {
                int r = wr * 32 + rg * 16 + lg + half * 8;
#pragma unroll
                for (int nf = 0; nf < 8; nf++) {
                    int col = wc * 64 + nf * 8 + 2 * lk;
                    Cs[col * CSTR + r]       = acc[rg][nf][half * 2 + 0] + sbias[col];
                    Cs[(col + 1) * CSTR + r] = acc[rg][nf][half * 2 + 1] + sbias[col + 1];
                }
            }
        __syncthreads();
        int bimg2 = row0 >> 12;
        int pix0 = row0 & 4095;
#pragma unroll
        for (int j = 0; j < 16; j++) {
            int f4 = tid + j * 256;
            int ch = f4 >> 5, p4 = (f4 & 31) * 4;
            float4 v = *(const float4*)(Cs + ch * CSTR + p4);
            *(float4*)(Cmat + (size_t)(bimg2 * 128 + ch) * 4096 + pix0 + p4) = v;
        }
        return;
    }

#pragma unroll
    for (int rg = 0; rg < 2; rg++)
#pragma unroll
        for (int half = 0; half < 2; half++) {
            int row = row0 + wr * 32 + rg * 16 + lg + half * 8;
            float* cr = Cmat + (size_t)row * 128;
#pragma unroll
            for (int nf = 0; nf < 8; nf++) {
                int col = wc * 64 + nf * 8 + 2 * lk;
                float2 o;
                o.x = acc[rg][nf][half * 2 + 0] + sbias[col];
                o.y = acc[rg][nf][half * 2 + 1] + sbias[col + 1];
                *(float2*)(cr + col) = o;
            }
        }
}

__global__ __launch_bounds__(256, 2) void mma_gemm_async(
        const float* __restrict__ A, const float* __restrict__ Bimg,
        const float* __restrict__ bias, float* __restrict__ Cmat,
        int M, int mode) {
    extern __shared__ float smem[];
    // B blob is stage-1 output (complete by PDL transitivity); A is the
    // immediate predecessor's output -> pdl=1 path.
    gemm_body(smem, A, Bimg, bias, Cmat, blockIdx.x * 128, mode, 1);
    (void)M;
}

// ---------------------------------------------------------------------------
// Fused stage 1: blocks 0..240 -> GEMM1 (NCHW x -> y interior);
// blocks 241..432 -> B blobs m=1..3; blocks 433..1440 -> border ring of y.
// All inputs external -> trigger dependents immediately.
// ---------------------------------------------------------------------------
__global__ __launch_bounds__(256, 2) void fused_prep_nchw(
        const float* __restrict__ A, const float* __restrict__ conv_w,
        const float* __restrict__ in_proj_w,
        const float* __restrict__ off_w, const float* __restrict__ off_b,
        const float* __restrict__ mask_w, const float* __restrict__ mask_b,
        const float* __restrict__ out_proj_w,
        const float* __restrict__ conv_b, int M) {
    extern __shared__ float smem[];
    int tid = threadIdx.x;
    int blk = blockIdx.x;
    GDC_LAUNCH();

    if (blk >= 241) {
        if (blk < 433) {
            int m = 1 + ((blk - 241) >> 6);
            int inner = (blk - 241) & 63;
            int idx = m * 16384 + inner * 256 + tid;
            int f = idx & 16383;
            int f4 = f >> 2, comp = f & 3;
            int lane_ = f4 & 31;
            int t = f4 >> 5;
            int q = t & 3; t >>= 2;
            int ks = t & 15;
            int wcx = t >> 4;
            int nf = 2 * q + (comp >> 1);
            int n = wcx * 64 + nf * 8 + (lane_ >> 2);
            int k = ks * 8 + (lane_ & 3) + ((comp & 1) << 2);
            float v = 0.f;
            if (m == 1) v = in_proj_w[k * CC + n];
            else if (m == 2) {
                if (n < 72)       v = off_w[k * 72 + n];
                else if (n < 108) v = mask_w[k * 36 + (n - 72)];
            } else v = out_proj_w[k * CC + n];
            ((uint32_t*)g_Bimg)[idx] = f2tf32(v);
            if (blk == 241 && tid < CC)
                g_bcomb[tid] = (tid < 72) ? off_b[tid]
                             : (tid < 108 ? mask_b[tid - 72] : 0.f);
        } else {
            int idx = (blk - 433) * 256 + tid;
            int b = idx / (252 * 128);
            int r = idx - b * (252 * 128);
            int pi = r >> 7, c = r & 127;
            int h, w;
            if (pi < 64)       { h = 0;        w = pi; }
            else if (pi < 128) { h = 63;       w = pi - 64; }
            else if (pi < 190) { h = pi - 127; w = 0; }
            else               { h = pi - 189; w = 63; }
            g_y[((size_t)(b * 4096 + h * 64 + w)) * 128 + c] = f2tf32f(conv_b[c]);
        }
        return;
    }

    // ---- NCHW GEMM tile ----
    float* sbias = smem + OFF_BIAS;
    int lane = tid & 31;
    int wid = tid >> 5;
    int row0 = blk * 128;

    if (tid < 128) sbias[tid] = conv_b[tid];

#pragma unroll
    for (int j = 0; j < 16; j++) {
        int f4i = tid + j * 256;
        int lane_ = f4i & 31;
        int t = f4i >> 5;
        int q = t & 3; t >>= 2;
        int ks = t & 15;
        int wcx = t >> 4;
        int lg_ = lane_ >> 2, lk_ = lane_ & 3;
        int n0 = wcx * 64 + (2 * q) * 8 + lg_;
        int n1 = n0 + 8;
        int k0 = ks * 8 + lk_;
        uint4 u;
        u.x = f2tf32(conv_w[n0 * 128 + k0]);
        u.y = f2tf32(conv_w[n0 * 128 + k0 + 4]);
        u.z = f2tf32(conv_w[n1 * 128 + k0]);
        u.w = f2tf32(conv_w[n1 * 128 + k0 + 4]);
        *(uint4*)(smem + OFF_B + f4i * 4) = u;
    }

    float rstage[16];
#define PREFETCH1(kc)                                                         \
do {                                                                          \
    int k0 = (kc) * 32;                                                       \
    _Pragma("unroll")                                                         \
    for (int j = 0; j < 16; j++) {                                            \
        int idx = tid + j * 256;                                              \
        int r = idx & 127, cl = idx >> 7;                                     \
        int grow = row0 + r; if (grow >= M) grow = M - 1;                     \
        int b = grow / 3844;                                                  \
        int s = grow - b * 3844;                                              \
        rstage[j] = A[(size_t)(b * 128 + k0 + cl) * 3844 + s];                \
    }                                                                         \
} while (0)
#define STORE1(buf)                                                           \
do {                                                                          \
    float* As_ = smem + ((buf) ? OFF_A1 : OFF_A0);                            \
    _Pragma("unroll")                                                         \
    for (int j = 0; j < 16; j++) {                                            \
        int idx = tid + j * 256;                                              \
        int r = idx & 127, cl = idx >> 7;                                     \
        ((uint32_t*)(As_ + r * ASTR + cl))[0] = f2tf32(rstage[j]);            \
    }                                                                         \
} while (0)

    PREFETCH1(0);
    STORE1(0);
    __syncthreads();

    int wr = wid >> 1;
    int wc = wid & 1;
    int lg = lane >> 2;
    int lk = lane & 3;
    DECL_ACC;

#pragma unroll
    for (int kc = 0; kc < 4; kc++) {
        if (kc < 3) PREFETCH1(kc + 1);
        COMPUTE_CHUNK(kc);
        if (kc < 3) {
            STORE1((kc + 1) & 1);
            __syncthreads();
        }
    }

#pragma unroll
    for (int rg = 0; rg < 2; rg++)
#pragma unroll
        for (int half = 0; half < 2; half++) {
            int row = row0 + wr * 32 + rg * 16 + lg + half * 8;
            if (row < M) {
                int b2 = row / 3844;
                int r = row - b2 * 3844;
                int hh = r / 62;
                int ww2 = r - hh * 62;
                float* cr = g_y + ((size_t)(b2 * 4096 + (hh + 1) * 64 + ww2 + 1)) * 128;
#pragma unroll
                for (int nf = 0; nf < 8; nf++) {
                    int col = wc * 64 + nf * 8 + 2 * lk;
                    float2 o;
                    o.x = f2tf32f(acc[rg][nf][half * 2 + 0] + sbias[col]);
                    o.y = f2tf32f(acc[rg][nf][half * 2 + 1] + sbias[col + 1]);
                    *(float2*)(cr + col) = o;
                }
            }
        }
#undef PREFETCH1
#undef STORE1
}

// ---------------------------------------------------------------------------
// dw body (tiled): blk in [0,512), 8x8 pixel tile, patch 10x10x128
// ---------------------------------------------------------------------------
__device__ __forceinline__ void dw_body(
        float* patch, int blk,
        const float* __restrict__ dw_w, const float* __restrict__ dw_b,
        const float* __restrict__ ln_g, const float* __restrict__ ln_b) {
    int b = blk >> 6;
    int tile = blk & 63;
    int h0 = (tile >> 3) * 8, w0 = (tile & 7) * 8;
    int tid = threadIdx.x;
    int lane = tid & 31;
    int warp = tid >> 5;

#pragma unroll
    for (int j = 0; j < 13; j++) {
        int idx = tid + j * 256;
        if (idx < 3200) {
            int pos = idx >> 5, q = idx & 31;
            int py = pos / 10, px = pos - py * 10;
            int hh = h0 - 1 + py, ww = w0 - 1 + px;
            bool valid = ((unsigned)hh < 64u) && ((unsigned)ww < 64u);
            int hc = valid ? hh : 0, wc2 = valid ? ww : 0;
            cp_async16_z(s2u(patch + pos * 128 + q * 4),
                         g_y + ((size_t)(b * 4096 + hc * 64 + wc2)) * 128 + q * 4,
                         valid ? 16 : 0);
        }
    }
    CP_COMMIT();

    int c0 = lane * 4;
    float4 wv[9];
#pragma unroll
    for (int t = 0; t < 9; t++) {
        wv[t].x = dw_w[(c0 + 0) * 9 + t];
        wv[t].y = dw_w[(c0 + 1) * 9 + t];
        wv[t].z = dw_w[(c0 + 2) * 9 + t];
        wv[t].w = dw_w[(c0 + 3) * 9 + t];
    }
    float4 bv = *(const float4*)(dw_b + c0);
    float4 gv = *(const float4*)(ln_g + c0);
    float4 lbv = *(const float4*)(ln_b + c0);

    CP_WAIT(0);
    __syncthreads();

#pragma unroll
    for (int i = 0; i < 8; i++) {
        int pix = warp * 8 + i;
        int py = pix >> 3, px = pix & 7;
        float4 acc = bv;
#pragma unroll
        for (int kh = 0; kh < 3; kh++)
#pragma unroll
            for (int kw = 0; kw < 3; kw++) {
                float4 v = *(const float4*)(patch + ((py + kh) * 10 + (px + kw)) * 128 + c0);
                acc.x += v.x * wv[kh * 3 + kw].x;
                acc.y += v.y * wv[kh * 3 + kw].y;
                acc.z += v.z * wv[kh * 3 + kw].z;
                acc.w += v.w * wv[kh * 3 + kw].w;
            }
        float s  = acc.x + acc.y + acc.z + acc.w;
        float s2 = acc.x * acc.x + acc.y * acc.y + acc.z * acc.z + acc.w * acc.w;
#pragma unroll
        for (int o = 16; o; o >>= 1) {
            s  += __shfl_xor_sync(0xffffffffu, s,  o);
            s2 += __shfl_xor_sync(0xffffffffu, s2, o);
        }
        float mu  = s * (1.f / 128.f);
        float var = s2 * (1.f / 128.f) - mu * mu;
        float rstd = rsqrtf(var + 1e-5f);
        float4 o4;
        float v0 = (acc.x - mu) * rstd * gv.x + lbv.x;
        float v1 = (acc.y - mu) * rstd * gv.y + lbv.y;
        float v2 = (acc.z - mu) * rstd * gv.z + lbv.z;
        float v3 = (acc.w - mu) * rstd * gv.w + lbv.w;
        o4.x = f2tf32f(0.5f * v0 * (1.f + erff(v0 * 0.70710678118654752440f)));
        o4.y = f2tf32f(0.5f * v1 * (1.f + erff(v1 * 0.70710678118654752440f)));
        o4.z = f2tf32f(0.5f * v2 * (1.f + erff(v2 * 0.70710678118654752440f)));
        o4.w = f2tf32f(0.5f * v3 * (1.f + erff(v3 * 0.70710678118654752440f)));
        size_t gp = (size_t)(b * 4096 + (h0 + py) * 64 + (w0 + px)) * 128 + c0;
        *(float4*)(g_d + gp) = o4;
    }
}

// ---------------------------------------------------------------------------
// Fused stage 2: blocks 0..255 -> in_proj GEMM (y->xproj);
//                blocks 256..767 -> dw+LN+GELU (y->d).
// Both branches read y (stage-1 output) and the m=1 blob (also stage-1):
// wait first, then trigger.
// ---------------------------------------------------------------------------
__global__ __launch_bounds__(256, 2) void fused_inproj_dw(
        const float* __restrict__ Bimg, const float* __restrict__ in_proj_b,
        const float* __restrict__ dw_w, const float* __restrict__ dw_b,
        const float* __restrict__ ln_g, const float* __restrict__ ln_b) {
    extern __shared__ float smem[];
    GDC_WAIT();
    GDC_LAUNCH();
    if (blockIdx.x < 256) {
        gemm_body(smem, g_y, Bimg, in_proj_b, g_xproj, blockIdx.x * 128, 0, 0);
    } else {
        dw_body(smem, blockIdx.x - 256, dw_w, dw_b, ln_g, ln_b);
    }
}

// ---------------------------------------------------------------------------
// Tiled DCNv3 core (R12 config): block = (tile, group). 2048 blocks,
// 14x14 halo-3 f32 patch. smem = 38,912 B -> 4 CTAs/SM hint.
// Patch reads xproj (2 stages back -> safe pre-wait); om after wait.
// ---------------------------------------------------------------------------
#define DCN_PATCH_OFF 0
#define DCN_MASK_OFF  6272
#define DCN_PLANW_OFF (6272 + 576)
#define DCN_PLANM_OFF (6272 + 576 + 2304)
#define DCN_SMEM_FLOATS (6272 + 576 + 2304 + 576)
#define DCN_SMEM_BYTES (DCN_SMEM_FLOATS * 4)

__global__ __launch_bounds__(256, 4) void dcn_core_tiled() {
    extern __shared__ float smem[];
    float* patch = smem + DCN_PATCH_OFF;             // [196][32]
    float* smask = smem + DCN_MASK_OFF;              // [64][9]
    float4* planw = (float4*)(smem + DCN_PLANW_OFF); // [576]
    int*    planm = (int*)(smem + DCN_PLANM_OFF);    // [576]
    int blk = blockIdx.x;
    int g = blk & 3;
    int tileid = blk >> 2;
    int b = tileid >> 6;
    int tile = tileid & 63;
    int h0 = (tile >> 3) * 8, w0 = (tile & 7) * 8;
    int tid = threadIdx.x;
    int lane = tid & 31;
    int warp = tid >> 5;
    const float* xp = g_xproj + (size_t)b * 4096 * 128;
    const float* omb = g_om + (size_t)b * 4096 * 128;

    // patch: xproj is complete before this kernel can launch (PDL
    // transitivity through stage 3's post-wait trigger) -> prelude.
#pragma unroll
    for (int j = 0; j < 7; j++) {
        int idx = tid + j * 256;
        if (idx < 1568) {
            int pos = idx >> 3, q = idx & 7;
            int py = pos / 14, px = pos - py * 14;
            int iy = h0 - 3 + py, ix = w0 - 3 + px;
            bool valid = ((unsigned)iy < 64u) && ((unsigned)ix < 64u);
            int yc = valid ? iy : 0, xc = valid ? ix : 0;
            cp_async16_z(s2u(patch + pos * 32 + q * 4),
                         xp + ((size_t)(yc * 64 + xc)) * 128 + g * 32 + q * 4,
                         valid ? 16 : 0);
        }
    }
    CP_COMMIT();
    GDC_WAIT();
    GDC_LAUNCH();

    // softmax for this group's mask: thread = pixel (direct global reads)
    if (tid < 64) {
        int lpix = (h0 + (tid >> 3)) * 64 + w0 + (tid & 7);
        const float* mp = omb + (size_t)lpix * 128 + 72 + g * 9;
        float v[9];
        float mx = -1e30f;
#pragma unroll
        for (int i = 0; i < 9; i++) { v[i] = mp[i]; mx = fmaxf(mx, v[i]); }
        float sum = 0.f;
#pragma unroll
        for (int i = 0; i < 9; i++) { v[i] = expf(v[i] - mx); sum += v[i]; }
        float inv = 1.f / sum;
#pragma unroll
        for (int i = 0; i < 9; i++) smask[tid * 9 + i] = v[i] * inv;
    }
    __syncthreads();

    // plan: 576 items = (pix, p); offsets read directly from global
#pragma unroll
    for (int j = 0; j < 3; j++) {
        int item = tid + j * 256;
        if (item < 576) {
            int pix = item / 9, p = item - pix * 9;
            int w = w0 + (pix & 7), h = h0 + (pix >> 3);
            int lpix = h * 64 + w;
            float2 off = *(const float2*)(omb + (size_t)lpix * 128 + (g * 9 + p) * 2);
            float mv = smask[pix * 9 + p];
            float ix = (float)(w + (p / 3)) + off.x;
            float iy = (float)(h + (p % 3)) + off.y;
            float x0f = floorf(ix), y0f = floorf(iy);
            int x0 = (int)x0f, y0 = (int)y0f;
            float fx = ix - x0f, fy = iy - y0f;
            float wx0 = 1.f - fx, wy0 = 1.f - fy;
            float4 wt;
            wt.x = mv * wx0 * wy0;
            wt.y = mv * fx  * wy0;
            wt.z = mv * wx0 * fy;
            wt.w = mv * fx  * fy;
            planw[item] = wt;
            int px0 = x0 - w0 + 2, py0 = y0 - h0 + 2;
            int meta;
            if ((unsigned)px0 <= 12u && (unsigned)py0 <= 12u) {
                meta = (py0 * 14 + px0) * 32;
            } else {
                int x0c = min(max(x0, -4), 68) + 4;
                int y0c = min(max(y0, -4), 68) + 4;
                meta = (int)(0x80000000u | (unsigned)(y0c << 8) | (unsigned)x0c);
            }
            planm[item] = meta;
        }
    }
    CP_WAIT(0);
    __syncthreads();

    // gather: warp -> 8 pixels, lane -> channel within group
#pragma unroll
    for (int i = 0; i < 8; i++) {
        int pix = warp * 8 + i;
        float acc = 0.f;
#pragma unroll
        for (int p = 0; p < 9; p++) {
            int item = pix * 9 + p;
            float4 wt = planw[item];
            int meta = planm[item];
            if (meta >= 0) {
                const float* pb = patch + meta + lane;
                acc += wt.x * pb[0];
                acc += wt.y * pb[32];
                acc += wt.z * pb[448];
                acc += wt.w * pb[480];
            } else {
                int x0 = (meta & 0xFF) - 4;
                int y0 = ((meta >> 8) & 0xFF) - 4;
                const float* base = xp + g * 32 + lane;
                if (y0 >= 1 && y0 <= 64) {
                    const float* r = base + (size_t)((y0 - 1) * 64) * 128;
                    if (x0 >= 1 && x0 <= 64) acc += wt.x * r[(size_t)(x0 - 1) * 128];
                    if (x0 >= 0 && x0 <= 63) acc += wt.y * r[(size_t)x0 * 128];
                }
                if (y0 >= 0 && y0 <= 63) {
                    const float* r = base + (size_t)(y0 * 64) * 128;
                    if (x0 >= 1 && x0 <= 64) acc += wt.z * r[(size_t)(x0 - 1) * 128];
                    if (x0 >= 0 && x0 <= 63) acc += wt.w * r[(size_t)x0 * 128];
                }
            }
        }
        int gpix = b * 4096 + (h0 + (pix >> 3)) * 64 + w0 + (pix & 7);
        g_samp[(size_t)gpix * 128 + g * 32 + lane] = f2tf32f(acc);
    }
}

// ---------------------------------------------------------------------------
extern "C" void kernel_launch(void* const* d_in, const int* in_sizes, int n_in,
                              void* d_out, int out_size) {
    const float* x          = (const float*)d_in[0];
    const float* conv_w     = (const float*)d_in[1];
    const float* conv_b     = (const float*)d_in[2];
    const float* in_proj_w  = (const float*)d_in[3];
    const float* in_proj_b  = (const float*)d_in[4];
    const float* dw_w       = (const float*)d_in[5];
    const float* dw_b       = (const float*)d_in[6];
    const float* ln_g       = (const float*)d_in[7];
    const float* ln_b       = (const float*)d_in[8];
    const float* off_w      = (const float*)d_in[9];
    const float* off_b      = (const float*)d_in[10];
    const float* mask_w     = (const float*)d_in[11];
    const float* mask_b     = (const float*)d_in[12];
    const float* out_proj_w = (const float*)d_in[13];
    const float* out_proj_b = (const float*)d_in[14];
    float* out = (float*)d_out;

    float *dbuf, *samp, *bimg, *bcb, *om;
    cudaGetSymbolAddress((void**)&dbuf, g_d);
    cudaGetSymbolAddress((void**)&samp, g_samp);
    cudaGetSymbolAddress((void**)&bimg, g_Bimg);
    cudaGetSymbolAddress((void**)&bcb,  g_bcomb);
    cudaGetSymbolAddress((void**)&om,   g_om);

    cudaFuncSetAttribute(mma_gemm_async,  cudaFuncAttributeMaxDynamicSharedMemorySize, SMEM_BYTES);
    cudaFuncSetAttribute(fused_prep_nchw, cudaFuncAttributeMaxDynamicSharedMemorySize, SMEM_BYTES);
    cudaFuncSetAttribute(fused_inproj_dw, cudaFuncAttributeMaxDynamicSharedMemorySize, SMEM_BYTES);
    cudaFuncSetAttribute(dcn_core_tiled,  cudaFuncAttributeMaxDynamicSharedMemorySize, DCN_SMEM_BYTES);

    const int M1 = BB*HS*WS;   // 30752
    const int M2 = BB*HH*WW;   // 32768

    // PDL launch config (programmatic stream serialization)
    cudaLaunchAttribute pdlAttr[1];
    pdlAttr[0].id = cudaLaunchAttributeProgrammaticStreamSerialization;
    pdlAttr[0].val.programmaticStreamSerializationAllowed = 1;

    // Stage 1 (normal launch; triggers dependents early)
    fused_prep_nchw<<<1441, 256, SMEM_BYTES>>>(x, conv_w, in_proj_w, off_w, off_b,
                                               mask_w, mask_b, out_proj_w, conv_b, M1);

    // Stage 2
    {
        cudaLaunchConfig_t cfg = {};
        cfg.gridDim = dim3(768, 1, 1);
        cfg.blockDim = dim3(256, 1, 1);
        cfg.dynamicSmemBytes = SMEM_BYTES;
        cfg.attrs = pdlAttr; cfg.numAttrs = 1;
        cudaLaunchKernelEx(&cfg, fused_inproj_dw,
                           (const float*)(bimg + 16384), in_proj_b,
                           dw_w, dw_b, ln_g, ln_b);
    }
    // Stage 3: om GEMM
    {
        cudaLaunchConfig_t cfg = {};
        cfg.gridDim = dim3(M2 / 128, 1, 1);
        cfg.blockDim = dim3(256, 1, 1);
        cfg.dynamicSmemBytes = SMEM_BYTES;
        cfg.attrs = pdlAttr; cfg.numAttrs = 1;
        cudaLaunchKernelEx(&cfg, mma_gemm_async,
                           (const float*)dbuf, (const float*)(bimg + 2*16384),
                           (const float*)bcb, om, M2, 0);
    }
    // Stage 4: dcn
    {
        cudaLaunchConfig_t cfg = {};
        cfg.gridDim = dim3(2048, 1, 1);
        cfg.blockDim = dim3(256, 1, 1);
        cfg.dynamicSmemBytes = DCN_SMEM_BYTES;
        cfg.attrs = pdlAttr; cfg.numAttrs = 1;
        cudaLaunchKernelEx(&cfg, dcn_core_tiled);
    }
    // Stage 5: out GEMM (NCHW epilogue)
    {
        cudaLaunchConfig_t cfg = {};
        cfg.gridDim = dim3(M2 / 128, 1, 1);
        cfg.blockDim = dim3(256, 1, 1);
        cfg.dynamicSmemBytes = SMEM_BYTES;
        cfg.attrs = pdlAttr; cfg.numAttrs = 1;
        cudaLaunchKernelEx(&cfg, mma_gemm_async,
                           (const float*)samp, (const float*)(bimg + 3*16384),
                           out_proj_b, out, M2, 2);
    }
}